// round 8
// baseline (speedup 1.0000x reference)
#include <cuda_runtime.h>
#include <stdint.h>

#define VGRID   64
#define G3      (VGRID * VGRID * VGRID)       // 262144
#define BMAX    8
#define CCH     96
#define NSEG    (BMAX * G3)                   // 2097152
#define CAP     16                            // max points kept per voxel

// Static state. g_cnt must be zero at kernel entry: zero at module load, and
// gather re-zeroes it each replay. g_bins slots are always rewritten before
// being read (first cnt[v] slots), so they need no clearing.
// Dataset note: coords are uniform random -> per-voxel counts ~Poisson(0.5);
// max over 2M voxels ~9. CAP=16 gives astronomical margin; slot>=CAP writes
// are dropped defensively.
__device__ int g_cnt[NSEG];
__device__ int g_bins[(size_t)NSEG * CAP];    // 134 MB

// ---------------------------------------------------------------------------
// K1: fused index + bin scatter. The histogram atomicAdd's return value IS
// the point's slot in its voxel bin — no prefix scan, no second pass.
// NOTE: *50.0f (not /0.02f) is load-bearing — XLA folds the reference's
// constant division into a multiply; dividing flips floor() at boundaries.
// ---------------------------------------------------------------------------
__global__ void index_bin_kernel(const float* __restrict__ coord,
                                 const int*   __restrict__ offset,
                                 const int*   __restrict__ resolution,
                                 int n, int nb) {
    int p = blockIdx.x * blockDim.x + threadIdx.x;
    if (p >= n) return;

    int b = 0;
    #pragma unroll
    for (int i = 0; i < BMAX; i++)
        if (i < nb && offset[i] <= p) b++;

    float fx = coord[3 * p + 0];
    float fy = coord[3 * p + 1];
    float fz = coord[3 * p + 2];
    float vx = floorf(fx * 50.0f);
    float vy = floorf(fy * 50.0f);
    float vz = floorf(fz * 50.0f);
    float cr = (float)(resolution[b] + 1);
    float sc = __fdiv_rn(cr, (float)VGRID);
    int gx = (int)floorf(__fdiv_rn(vx, sc));
    int gy = (int)floorf(__fdiv_rn(vy, sc));
    int gz = (int)floorf(__fdiv_rn(vz, sc));
    gx = min(max(gx, 0), VGRID - 1);
    gy = min(max(gy, 0), VGRID - 1);
    gz = min(max(gz, 0), VGRID - 1);

    int sp  = (gz * VGRID + gy) * VGRID + gx;   // output spatial order (z,y,x)
    int seg = b * G3 + sp;
    int slot = atomicAdd(&g_cnt[seg], 1);
    if (slot < CAP)
        g_bins[(size_t)seg * CAP + slot] = p;
}

// ---------------------------------------------------------------------------
// K2: gather + mean + transpose + output. One block per 32 voxels.
// 8 threads/voxel, each owning 12 channels (3 float4 accumulators); feat rows
// read in coalesced 128B groups. Transpose via FSTRIDE-97 smem (conflict-free
// scalar STS: bank = 4g+q+r; conflict-free scalar LDS: bank = 4xq+j+c), then
// STG.128 output stores. Re-zeroes g_cnt for the next replay.
// ---------------------------------------------------------------------------
#define FSTRIDE 97

__global__ void gather_kernel(const float* __restrict__ feat,
                              float* __restrict__ out) {
    __shared__ float tile[32 * FSTRIDE];
    __shared__ int   s_k[32];
    __shared__ float s_rinv[32];

    int vbase = blockIdx.x * 32;             // 32 consecutive segs; one b/block
    int tid   = threadIdx.x;

    if (tid < 32) {
        int v = vbase + tid;
        int k = g_cnt[v];
        s_k[tid]    = min(k, CAP);
        s_rinv[tid] = (k > 0) ? __fdiv_rn(1.0f, (float)k) : 0.0f;
        g_cnt[v] = 0;                        // reset for next replay
    }
    __syncthreads();

    int r = tid >> 3;                        // local voxel 0..31
    int g = tid & 7;                         // float4 slot 0..7
    int k    = s_k[r];
    float ri = s_rinv[r];
    const int* __restrict__ bin = g_bins + (size_t)(vbase + r) * CAP;

    float4 a0 = make_float4(0.f, 0.f, 0.f, 0.f);
    float4 a1 = a0, a2 = a0;
    for (int i = 0; i < k; i++) {
        int pid = bin[i];                    // broadcast across the 8 threads
        const float4* frow = (const float4*)(feat + (size_t)pid * CCH);
        float4 f0 = __ldcs(frow + g);
        float4 f1 = __ldcs(frow + g + 8);
        float4 f2 = __ldcs(frow + g + 16);
        a0.x += f0.x; a0.y += f0.y; a0.z += f0.z; a0.w += f0.w;
        a1.x += f1.x; a1.y += f1.y; a1.z += f1.z; a1.w += f1.w;
        a2.x += f2.x; a2.y += f2.y; a2.z += f2.z; a2.w += f2.w;
    }
    a0.x *= ri; a0.y *= ri; a0.z *= ri; a0.w *= ri;
    a1.x *= ri; a1.y *= ri; a1.z *= ri; a1.w *= ri;
    a2.x *= ri; a2.y *= ri; a2.z *= ri; a2.w *= ri;

    int base = r * FSTRIDE + g * 4;
    tile[base +  0] = a0.x; tile[base +  1] = a0.y;
    tile[base +  2] = a0.z; tile[base +  3] = a0.w;
    tile[base + 32] = a1.x; tile[base + 33] = a1.y;
    tile[base + 34] = a1.z; tile[base + 35] = a1.w;
    tile[base + 64] = a2.x; tile[base + 65] = a2.y;
    tile[base + 66] = a2.z; tile[base + 67] = a2.w;
    __syncthreads();

    // Write phase: 768 float4 stores per block, 3 per thread.
    // idx -> channel c = idx>>3, x-quad xq = idx&7; out[b][c][sp0 + 4xq .. +3].
    int b   = vbase >> 18;                   // / G3
    int sp0 = vbase & (G3 - 1);
    #pragma unroll
    for (int m = 0; m < 3; m++) {
        int idx = tid + 256 * m;
        int c   = idx >> 3;
        int xq  = idx & 7;
        float4 v4;
        v4.x = tile[(4 * xq + 0) * FSTRIDE + c];
        v4.y = tile[(4 * xq + 1) * FSTRIDE + c];
        v4.z = tile[(4 * xq + 2) * FSTRIDE + c];
        v4.w = tile[(4 * xq + 3) * FSTRIDE + c];
        __stcs((float4*)(out + ((size_t)(b * CCH + c)) * G3 + sp0 + 4 * xq), v4);
    }
}

// ---------------------------------------------------------------------------
extern "C" void kernel_launch(void* const* d_in, const int* in_sizes, int n_in,
                              void* d_out, int out_size) {
    const float* coord      = (const float*)d_in[0];
    const float* feat       = (const float*)d_in[1];
    const int*   offset     = (const int*)d_in[2];
    const int*   resolution = (const int*)d_in[3];
    float*       out        = (float*)d_out;

    int n  = in_sizes[0] / 3;
    int nb = in_sizes[2];
    if (nb > BMAX) nb = BMAX;

    index_bin_kernel<<<(n + 255) / 256, 256>>>(coord, offset, resolution, n, nb);
    gather_kernel<<<nb * (G3 / 32), 256>>>(feat, out);
}

// round 9
// speedup vs baseline: 1.2626x; 1.2626x over previous
#include <cuda_runtime.h>
#include <stdint.h>

#define VGRID   64
#define G3      (VGRID * VGRID * VGRID)       // 262144
#define BMAX    8
#define CCH     96
#define NMAX    (BMAX * 131072)               // 1048576
#define NSEG    (BMAX * G3)                   // 2097152

#define SCAN_TPB    256
#define SCAN_EPT    8
#define SCAN_CHUNK  (SCAN_TPB * SCAN_EPT)     // 2048
#define SCAN_BLOCKS (NSEG / SCAN_CHUNK)       // 1024

// All state re-derived every replay. g_cnt must be zero at entry: zero at
// module load; gather re-zeroes it each replay.
__device__ int g_seg[NMAX];
__device__ int g_cnt[NSEG];
__device__ int g_pos[NSEG];      // exclusive starts; becomes ends after scatter
__device__ int g_bsum[SCAN_BLOCKS];
__device__ int g_sorted[NMAX];   // dense: voxel v's points at [start(v), end(v))

// ---------------------------------------------------------------------------
// K1: per-point segment id + int histogram.
// NOTE: *50.0f (not /0.02f) is load-bearing — XLA folds the reference's
// constant division into a multiply; dividing flips floor() at boundaries.
// ---------------------------------------------------------------------------
__global__ void index_kernel(const float* __restrict__ coord,
                             const int*   __restrict__ offset,
                             const int*   __restrict__ resolution,
                             int n, int nb) {
    int p = blockIdx.x * blockDim.x + threadIdx.x;
    if (p >= n) return;

    int b = 0;
    #pragma unroll
    for (int i = 0; i < BMAX; i++)
        if (i < nb && offset[i] <= p) b++;

    float fx = coord[3 * p + 0];
    float fy = coord[3 * p + 1];
    float fz = coord[3 * p + 2];
    float vx = floorf(fx * 50.0f);
    float vy = floorf(fy * 50.0f);
    float vz = floorf(fz * 50.0f);
    float cr = (float)(resolution[b] + 1);
    float sc = __fdiv_rn(cr, (float)VGRID);
    int gx = (int)floorf(__fdiv_rn(vx, sc));
    int gy = (int)floorf(__fdiv_rn(vy, sc));
    int gz = (int)floorf(__fdiv_rn(vz, sc));
    gx = min(max(gx, 0), VGRID - 1);
    gy = min(max(gy, 0), VGRID - 1);
    gz = min(max(gz, 0), VGRID - 1);

    int sp  = (gz * VGRID + gy) * VGRID + gx;   // output spatial order (z,y,x)
    int seg = b * G3 + sp;
    g_seg[p] = seg;
    atomicAdd(&g_cnt[seg], 1);
}

// ---------------------------------------------------------------------------
// K2a: per-block reduction of 2048 counts -> g_bsum[block]
// ---------------------------------------------------------------------------
__global__ void scan_reduce_kernel() {
    __shared__ int ws[SCAN_TPB / 32];
    int tid  = threadIdx.x;
    int base = blockIdx.x * SCAN_CHUNK + tid * SCAN_EPT;
    int4 a = *(const int4*)(g_cnt + base);
    int4 c = *(const int4*)(g_cnt + base + 4);
    int s = a.x + a.y + a.z + a.w + c.x + c.y + c.z + c.w;
    #pragma unroll
    for (int d = 16; d > 0; d >>= 1) s += __shfl_down_sync(0xffffffffu, s, d);
    if ((tid & 31) == 0) ws[tid >> 5] = s;
    __syncthreads();
    if (tid == 0) {
        int t = 0;
        #pragma unroll
        for (int i = 0; i < SCAN_TPB / 32; i++) t += ws[i];
        g_bsum[blockIdx.x] = t;
    }
}

// ---------------------------------------------------------------------------
// K2b: single-block exclusive scan of the 1024 block sums (in place).
// ---------------------------------------------------------------------------
__global__ void scan_base_kernel() {
    __shared__ int win[32], wout[32];
    int tid  = threadIdx.x;          // 0..1023
    int lane = tid & 31, w = tid >> 5;
    int v = g_bsum[tid];
    int x = v;
    #pragma unroll
    for (int d = 1; d < 32; d <<= 1) {
        int y = __shfl_up_sync(0xffffffffu, x, d);
        if (lane >= d) x += y;
    }
    if (lane == 31) win[w] = x;
    __syncthreads();
    if (tid == 0) {
        int r = 0;
        #pragma unroll
        for (int i = 0; i < 32; i++) { wout[i] = r; r += win[i]; }
    }
    __syncthreads();
    g_bsum[tid] = x - v + wout[w];   // exclusive
}

// ---------------------------------------------------------------------------
// K2c: full exclusive scan; writes g_pos[i] = global exclusive prefix of cnt.
// ---------------------------------------------------------------------------
__global__ void scan_write_kernel() {
    __shared__ int win[SCAN_TPB / 32], wout[SCAN_TPB / 32];
    int tid  = threadIdx.x;
    int lane = tid & 31, w = tid >> 5;
    int base = blockIdx.x * SCAN_CHUNK + tid * SCAN_EPT;

    int4 a = *(const int4*)(g_cnt + base);
    int4 c = *(const int4*)(g_cnt + base + 4);
    int v[8] = {a.x, a.y, a.z, a.w, c.x, c.y, c.z, c.w};
    int pre[8];
    int run = 0;
    #pragma unroll
    for (int i = 0; i < 8; i++) { pre[i] = run; run += v[i]; }
    int tot = run;

    int x = tot;
    #pragma unroll
    for (int d = 1; d < 32; d <<= 1) {
        int y = __shfl_up_sync(0xffffffffu, x, d);
        if (lane >= d) x += y;
    }
    if (lane == 31) win[w] = x;
    __syncthreads();
    if (tid == 0) {
        int r = 0;
        #pragma unroll
        for (int i = 0; i < SCAN_TPB / 32; i++) { wout[i] = r; r += win[i]; }
    }
    __syncthreads();
    int off = g_bsum[blockIdx.x] + wout[w] + (x - tot);

    int4 o0 = make_int4(off + pre[0], off + pre[1], off + pre[2], off + pre[3]);
    int4 o1 = make_int4(off + pre[4], off + pre[5], off + pre[6], off + pre[7]);
    *(int4*)(g_pos + base)     = o0;
    *(int4*)(g_pos + base + 4) = o1;
}

// ---------------------------------------------------------------------------
// K3: scatter point ids into contiguous per-voxel runs.
// Mutates g_pos: after this, g_pos[v] == end of run v (start = end - cnt).
// ---------------------------------------------------------------------------
__global__ void scatter_kernel(int n) {
    int p = blockIdx.x * blockDim.x + threadIdx.x;
    if (p >= n) return;
    int seg = g_seg[p];
    int pos = atomicAdd(&g_pos[seg], 1);
    g_sorted[pos] = p;
}

// ---------------------------------------------------------------------------
// K4: gather + mean + transpose + output. One block per 32 consecutive voxels.
// The 32 voxels' sorted runs are CONTIGUOUS in g_sorted -> stage the whole
// run into smem with coalesced loads, then the 8-threads-per-voxel loop pulls
// pids from smem (no dependent scattered global loads in the hot loop).
// Ends with STG.128 transposed output stores. Re-zeroes g_cnt.
// ---------------------------------------------------------------------------
#define FSTRIDE 97
#define STAGE   128   // staged pids per block (avg run = 16; global fallback)

__global__ void gather_kernel(const float* __restrict__ feat,
                              float* __restrict__ out) {
    __shared__ float tile[32 * FSTRIDE];
    __shared__ int   s_loc[32], s_k[32];     // run start relative to block base
    __shared__ float s_rinv[32];
    __shared__ int   s_pid[STAGE];
    __shared__ int   s_base[2];              // [0]=blockStart, [1]=blockTotal

    int vbase = blockIdx.x * 32;
    int tid   = threadIdx.x;

    if (tid < 32) {
        int v = vbase + tid;
        int k = g_cnt[v];
        int e = g_pos[v];                    // end after scatter
        s_k[tid]    = k;
        s_rinv[tid] = (k > 0) ? __fdiv_rn(1.0f, (float)k) : 0.0f;
        g_cnt[v] = 0;                        // reset for next replay
        // block-local exclusive offsets via warp scan of k
        int x = k;
        #pragma unroll
        for (int d = 1; d < 32; d <<= 1) {
            int y = __shfl_up_sync(0xffffffffu, x, d);
            if (tid >= d) x += y;
        }
        s_loc[tid] = x - k;
        if (tid == 31) {
            s_base[0] = e - x;               // block run start in g_sorted
            s_base[1] = x;                   // total points in block
        }
    }
    __syncthreads();

    int bstart = s_base[0];
    int btotal = s_base[1];
    // Stage the contiguous run (coalesced). Beyond STAGE: fallback below.
    for (int i = tid; i < btotal && i < STAGE; i += 256)
        s_pid[i] = g_sorted[bstart + i];
    __syncthreads();

    int r = tid >> 3;                        // local voxel 0..31
    int g = tid & 7;                         // float4 slot 0..7
    int k    = s_k[r];
    int loc  = s_loc[r];
    float ri = s_rinv[r];

    float4 a0 = make_float4(0.f, 0.f, 0.f, 0.f);
    float4 a1 = a0, a2 = a0;
    for (int i = 0; i < k; i++) {
        int idx = loc + i;
        int pid = (idx < STAGE) ? s_pid[idx] : g_sorted[bstart + idx];
        const float4* frow = (const float4*)(feat + (size_t)pid * CCH);
        float4 f0 = __ldcs(frow + g);
        float4 f1 = __ldcs(frow + g + 8);
        float4 f2 = __ldcs(frow + g + 16);
        a0.x += f0.x; a0.y += f0.y; a0.z += f0.z; a0.w += f0.w;
        a1.x += f1.x; a1.y += f1.y; a1.z += f1.z; a1.w += f1.w;
        a2.x += f2.x; a2.y += f2.y; a2.z += f2.z; a2.w += f2.w;
    }
    a0.x *= ri; a0.y *= ri; a0.z *= ri; a0.w *= ri;
    a1.x *= ri; a1.y *= ri; a1.z *= ri; a1.w *= ri;
    a2.x *= ri; a2.y *= ri; a2.z *= ri; a2.w *= ri;

    int base = r * FSTRIDE + g * 4;
    tile[base +  0] = a0.x; tile[base +  1] = a0.y;
    tile[base +  2] = a0.z; tile[base +  3] = a0.w;
    tile[base + 32] = a1.x; tile[base + 33] = a1.y;
    tile[base + 34] = a1.z; tile[base + 35] = a1.w;
    tile[base + 64] = a2.x; tile[base + 65] = a2.y;
    tile[base + 66] = a2.z; tile[base + 67] = a2.w;
    __syncthreads();

    // Write phase: 768 float4 stores per block, 3 per thread (STG.128).
    // Bank for lane: 4*xq + j + c (mod 32) — conflict-free.
    int b   = vbase >> 18;                   // / G3
    int sp0 = vbase & (G3 - 1);
    #pragma unroll
    for (int m = 0; m < 3; m++) {
        int idx = tid + 256 * m;
        int c   = idx >> 3;
        int xq  = idx & 7;
        float4 v4;
        v4.x = tile[(4 * xq + 0) * FSTRIDE + c];
        v4.y = tile[(4 * xq + 1) * FSTRIDE + c];
        v4.z = tile[(4 * xq + 2) * FSTRIDE + c];
        v4.w = tile[(4 * xq + 3) * FSTRIDE + c];
        __stcs((float4*)(out + ((size_t)(b * CCH + c)) * G3 + sp0 + 4 * xq), v4);
    }
}

// ---------------------------------------------------------------------------
extern "C" void kernel_launch(void* const* d_in, const int* in_sizes, int n_in,
                              void* d_out, int out_size) {
    const float* coord      = (const float*)d_in[0];
    const float* feat       = (const float*)d_in[1];
    const int*   offset     = (const int*)d_in[2];
    const int*   resolution = (const int*)d_in[3];
    float*       out        = (float*)d_out;

    int n  = in_sizes[0] / 3;
    int nb = in_sizes[2];
    if (nb > BMAX) nb = BMAX;

    index_kernel<<<(n + 255) / 256, 256>>>(coord, offset, resolution, n, nb);
    scan_reduce_kernel<<<SCAN_BLOCKS, SCAN_TPB>>>();
    scan_base_kernel<<<1, SCAN_BLOCKS>>>();
    scan_write_kernel<<<SCAN_BLOCKS, SCAN_TPB>>>();
    scatter_kernel<<<(n + 255) / 256, 256>>>(n);
    gather_kernel<<<NSEG / 32, 256>>>(feat, out);
}